// round 2
// baseline (speedup 1.0000x reference)
#include <cuda_runtime.h>

#define NN   50000
#define EE   800000
#define INC  32
#define HIDC 64

// Scratch (device globals — no allocation allowed in kernel_launch)
__device__ __align__(16) float g_deg[NN];
__device__ __align__(16) float g_agg[NN * HIDC];
__device__ __align__(16) float g_h[NN * HIDC];

__device__ __forceinline__ void red_add_v4(float* p, float4 v) {
    asm volatile("red.global.add.v4.f32 [%0], {%1,%2,%3,%4};"
                 :: "l"(p), "f"(v.x), "f"(v.y), "f"(v.z), "f"(v.w)
                 : "memory");
}

// ---------------------------------------------------------------------------
// Zero kernels (agg/deg must be re-initialized every replay)
// ---------------------------------------------------------------------------
__global__ void k_zero1() {
    int idx = blockIdx.x * blockDim.x + threadIdx.x;
    const int nAgg = NN * INC / 4;     // 400000
    const int nDeg = NN / 4;           // 12500
    if (idx < nAgg) {
        ((float4*)g_agg)[idx] = make_float4(0.f, 0.f, 0.f, 0.f);
    } else if (idx < nAgg + nDeg) {
        ((float4*)g_deg)[idx - nAgg] = make_float4(0.f, 0.f, 0.f, 0.f);
    }
}

__global__ void k_zero2() {
    int idx = blockIdx.x * blockDim.x + threadIdx.x;
    const int nAgg = NN * HIDC / 4;    // 800000
    if (idx < nAgg) {
        ((float4*)g_agg)[idx] = make_float4(0.f, 0.f, 0.f, 0.f);
    }
}

// ---------------------------------------------------------------------------
// Scatter 1: agg[dst, 0:32] += x[src, 0:32]; deg[dst] += 1
// 8 threads per edge, 4 channels each.
// ---------------------------------------------------------------------------
__global__ void k_scatter1(const float* __restrict__ x,
                           const int* __restrict__ src,
                           const int* __restrict__ dst) {
    int idx = blockIdx.x * blockDim.x + threadIdx.x;
    if (idx >= EE * 8) return;
    int e = idx >> 3;
    int q = idx & 7;
    int s = __ldg(&src[e]);
    int d = __ldg(&dst[e]);
    float4 v = __ldg((const float4*)x + (long long)s * 8 + q);
    red_add_v4(&g_agg[(long long)d * INC + q * 4], v);
    if (q == 0) atomicAdd(&g_deg[d], 1.0f);
}

// ---------------------------------------------------------------------------
// Layer 1: h = relu( bn1( (agg*deg_inv) @ W1l + b1l + x @ W1r ) )
// One thread per node. Weights transposed [o][i] in shared, read as float4.
// BN folded: alpha = g*rsqrt(v+eps); beta = (b1l - m)*alpha + bn_b
// ---------------------------------------------------------------------------
__global__ __launch_bounds__(256)
void k_layer1(const float* __restrict__ x,
              const float* __restrict__ W1l, const float* __restrict__ b1l,
              const float* __restrict__ W1r,
              const float* __restrict__ g1, const float* __restrict__ bb1,
              const float* __restrict__ m1, const float* __restrict__ v1) {
    __shared__ float swl[HIDC * INC];   // [o][i]
    __shared__ float swr[HIDC * INC];
    __shared__ float alpha[HIDC], beta[HIDC];

    int tid = threadIdx.x;
    for (int t = tid; t < HIDC * INC; t += blockDim.x) {
        int o = t >> 5, i = t & 31;
        swl[t] = W1l[i * HIDC + o];
        swr[t] = W1r[i * HIDC + o];
    }
    if (tid < HIDC) {
        float a = g1[tid] * rsqrtf(v1[tid] + 1e-5f);
        alpha[tid] = a;
        beta[tid]  = (b1l[tid] - m1[tid]) * a + bb1[tid];
    }
    __syncthreads();

    int n = blockIdx.x * blockDim.x + tid;
    if (n >= NN) return;

    float dinv = 1.0f / fmaxf(g_deg[n], 1.0f);
    float a[INC], xr[INC];
    const float4* av = (const float4*)&g_agg[(long long)n * INC];
    const float4* xv = (const float4*)&x[(long long)n * INC];
#pragma unroll
    for (int j = 0; j < 8; j++) {
        float4 t1 = av[j];
        a[4*j+0] = t1.x * dinv; a[4*j+1] = t1.y * dinv;
        a[4*j+2] = t1.z * dinv; a[4*j+3] = t1.w * dinv;
        float4 t2 = xv[j];
        xr[4*j+0] = t2.x; xr[4*j+1] = t2.y; xr[4*j+2] = t2.z; xr[4*j+3] = t2.w;
    }

    float4* hv = (float4*)&g_h[(long long)n * HIDC];
    const float4* wl4 = (const float4*)swl;
    const float4* wr4 = (const float4*)swr;

#pragma unroll 1
    for (int og = 0; og < 16; og++) {
        float res[4];
#pragma unroll
        for (int k = 0; k < 4; k++) {
            int o = og * 4 + k;
            float acc = 0.f;
#pragma unroll
            for (int j = 0; j < 8; j++) {
                float4 wl = wl4[o * 8 + j];
                float4 wr = wr4[o * 8 + j];
                acc += a[4*j+0]*wl.x + a[4*j+1]*wl.y + a[4*j+2]*wl.z + a[4*j+3]*wl.w;
                acc += xr[4*j+0]*wr.x + xr[4*j+1]*wr.y + xr[4*j+2]*wr.z + xr[4*j+3]*wr.w;
            }
            res[k] = fmaxf(acc * alpha[o] + beta[o], 0.0f);
        }
        hv[og] = make_float4(res[0], res[1], res[2], res[3]);
    }
}

// ---------------------------------------------------------------------------
// Scatter 2: agg[dst, 0:64] += h[src, 0:64]
// 16 threads per edge, 4 channels each.
// ---------------------------------------------------------------------------
__global__ void k_scatter2(const int* __restrict__ src,
                           const int* __restrict__ dst) {
    int idx = blockIdx.x * blockDim.x + threadIdx.x;
    if (idx >= EE * 16) return;
    int e = idx >> 4;
    int q = idx & 15;
    int s = __ldg(&src[e]);
    int d = __ldg(&dst[e]);
    float4 v = __ldg((const float4*)g_h + (long long)s * 16 + q);
    red_add_v4(&g_agg[(long long)d * HIDC + q * 4], v);
}

// ---------------------------------------------------------------------------
// Layer 2 + head: h2 = relu(bn2((agg2*dinv)@W2l + b2l + h@W2r));
//                 out = h2 @ Wlin + blin
// ---------------------------------------------------------------------------
__global__ __launch_bounds__(128)
void k_layer2(const float* __restrict__ W2l, const float* __restrict__ b2l,
              const float* __restrict__ W2r,
              const float* __restrict__ g2, const float* __restrict__ bb2,
              const float* __restrict__ m2, const float* __restrict__ v2,
              const float* __restrict__ Wlin, const float* __restrict__ blin,
              float* __restrict__ out) {
    __shared__ float swl[HIDC * HIDC];   // [o][i] 16KB
    __shared__ float swr[HIDC * HIDC];   // 16KB
    __shared__ float alpha[HIDC], beta[HIDC], swo[HIDC];

    int tid = threadIdx.x;
    for (int t = tid; t < HIDC * HIDC; t += blockDim.x) {
        int o = t >> 6, i = t & 63;
        swl[t] = W2l[i * HIDC + o];
        swr[t] = W2r[i * HIDC + o];
    }
    if (tid < HIDC) {
        float a = g2[tid] * rsqrtf(v2[tid] + 1e-5f);
        alpha[tid] = a;
        beta[tid]  = (b2l[tid] - m2[tid]) * a + bb2[tid];
        swo[tid]   = Wlin[tid];
    }
    __syncthreads();

    int n = blockIdx.x * blockDim.x + tid;
    if (n >= NN) return;

    float dinv = 1.0f / fmaxf(g_deg[n], 1.0f);
    float a[HIDC], hh[HIDC];
    const float4* av = (const float4*)&g_agg[(long long)n * HIDC];
    const float4* hv = (const float4*)&g_h[(long long)n * HIDC];
#pragma unroll
    for (int j = 0; j < 16; j++) {
        float4 t1 = av[j];
        a[4*j+0] = t1.x * dinv; a[4*j+1] = t1.y * dinv;
        a[4*j+2] = t1.z * dinv; a[4*j+3] = t1.w * dinv;
        float4 t2 = hv[j];
        hh[4*j+0] = t2.x; hh[4*j+1] = t2.y; hh[4*j+2] = t2.z; hh[4*j+3] = t2.w;
    }

    const float4* wl4 = (const float4*)swl;
    const float4* wr4 = (const float4*)swr;
    float oacc = blin[0];

#pragma unroll 1
    for (int o = 0; o < HIDC; o++) {
        float acc = 0.f;
#pragma unroll
        for (int j = 0; j < 16; j++) {
            float4 wl = wl4[o * 16 + j];
            float4 wr = wr4[o * 16 + j];
            acc += a[4*j+0]*wl.x + a[4*j+1]*wl.y + a[4*j+2]*wl.z + a[4*j+3]*wl.w;
            acc += hh[4*j+0]*wr.x + hh[4*j+1]*wr.y + hh[4*j+2]*wr.z + hh[4*j+3]*wr.w;
        }
        float val = fmaxf(acc * alpha[o] + beta[o], 0.0f);
        oacc += val * swo[o];
    }
    out[n] = oacc;
}

// ---------------------------------------------------------------------------
// Launch
// ---------------------------------------------------------------------------
extern "C" void kernel_launch(void* const* d_in, const int* in_sizes, int n_in,
                              void* d_out, int out_size) {
    const float* x   = (const float*)d_in[0];
    const int*   ei  = (const int*)d_in[1];   // int32: jax x64 disabled
    const int*   src = ei;
    const int*   dst = ei + EE;
    const float* W1l  = (const float*)d_in[2];
    const float* b1l  = (const float*)d_in[3];
    const float* W1r  = (const float*)d_in[4];
    const float* bn1g = (const float*)d_in[5];
    const float* bn1b = (const float*)d_in[6];
    const float* bn1m = (const float*)d_in[7];
    const float* bn1v = (const float*)d_in[8];
    const float* W2l  = (const float*)d_in[9];
    const float* b2l  = (const float*)d_in[10];
    const float* W2r  = (const float*)d_in[11];
    const float* bn2g = (const float*)d_in[12];
    const float* bn2b = (const float*)d_in[13];
    const float* bn2m = (const float*)d_in[14];
    const float* bn2v = (const float*)d_in[15];
    const float* Wlin = (const float*)d_in[16];
    const float* blin = (const float*)d_in[17];
    float* out = (float*)d_out;

    // Layer 1
    {
        int n1 = NN * INC / 4 + NN / 4;           // 412500
        k_zero1<<<(n1 + 255) / 256, 256>>>();
        k_scatter1<<<(EE * 8) / 256, 256>>>(x, src, dst);
        k_layer1<<<(NN + 255) / 256, 256>>>(x, W1l, b1l, W1r, bn1g, bn1b, bn1m, bn1v);
    }
    // Layer 2 + head
    {
        int n2 = NN * HIDC / 4;                   // 800000
        k_zero2<<<(n2 + 255) / 256, 256>>>();
        k_scatter2<<<(EE * 16) / 256, 256>>>(src, dst);
        k_layer2<<<(NN + 127) / 128, 128>>>(W2l, b2l, W2r, bn2g, bn2b, bn2m, bn2v,
                                            Wlin, blin, out);
    }
}